// round 10
// baseline (speedup 1.0000x reference)
#include <cuda_runtime.h>

#define C_   16
#define GX_  36
#define GY_  36
#define RF_  24
#define IMG_ 64
#define G_   (GX_ * GY_)        // 1296
#define NITEMS (G_ * C_)        // 20736
#define GAMMA_E 0.9f
#define GAMMA_I 0.9f
#define NSM_  148
#define CTAS_ (NSM_ * 16)       // 2368 = full residency, single wave

// Combined partial per (ij,c): aff + ge*p*exc - gi*p*inh.
// Layout [ij][c]: each ij's 16 partials are one contiguous 64B span.
__device__ float g_part[G_ * C_];

__global__ __launch_bounds__(128, 16)
void cortex_partial(const float* __restrict__ x,
                    const float* __restrict__ prev,
                    const float* __restrict__ aw,
                    const float* __restrict__ ew,
                    const float* __restrict__ iw,
                    const int*   __restrict__ rx,
                    const int*   __restrict__ ry)
{
    const int t = threadIdx.x;
    const unsigned FULL = 0xFFFFFFFFu;
    __shared__ float s_red[3][4];

    // Persistent CTA: loop over work items strided by grid size.
    for (int item = blockIdx.x; item < NITEMS; item += CTAS_) {
        const int c  = item / G_;
        const int ij = item - c * G_;
        const int i  = ij / GY_;
        const int j  = ij - i * GY_;

        // ---- Lateral row sums (324 float4 per tensor, streamed once) ----
        const size_t rowbase = (size_t)(c * G_ + ij) * G_;
        const float4* e4 = reinterpret_cast<const float4*>(ew + rowbase);
        const float4* i4 = reinterpret_cast<const float4*>(iw + rowbase);
        float se = 0.f, si = 0.f;
        const int NF4 = G_ / 4;              // 324
        #pragma unroll
        for (int o = t; o < NF4; o += 128) {
            const float4 ve = __ldcs(e4 + o);
            const float4 vi = __ldcs(i4 + o);
            se += (ve.x + ve.y) + (ve.z + ve.w);
            si += (vi.x + vi.y) + (vi.z + vi.w);
        }

        // ---- Afferent (144 float4; x is L1/L2-resident) ----
        float aff = 0.f;
        const int rxi = __ldg(rx + i), ryj = __ldg(ry + j);
        const float4* a4 = reinterpret_cast<const float4*>(
            aw + (size_t)(c * G_ + ij) * (RF_ * RF_));
        #pragma unroll
        for (int o = t; o < (RF_ * RF_) / 4; o += 128) {
            const float4 w4 = __ldcs(a4 + o);
            const int uv = o * 4;
            const int u  = uv / RF_;
            const int v  = uv - u * RF_;
            const float* xr = x + c * IMG_ * IMG_ + (rxi + u) * IMG_ + (ryj + v);
            aff += w4.x * __ldg(xr + 0) + w4.y * __ldg(xr + 1)
                 + w4.z * __ldg(xr + 2) + w4.w * __ldg(xr + 3);
        }

        // ---- Block reduce (128 threads = 4 warps) ----
        #pragma unroll
        for (int off = 16; off > 0; off >>= 1) {
            aff += __shfl_down_sync(FULL, aff, off);
            se  += __shfl_down_sync(FULL, se,  off);
            si  += __shfl_down_sync(FULL, si,  off);
        }
        const int wid = t >> 5, lid = t & 31;
        if (lid == 0) { s_red[0][wid] = aff; s_red[1][wid] = se; s_red[2][wid] = si; }
        __syncthreads();

        if (t == 0) {
            const float a = s_red[0][0] + s_red[0][1] + s_red[0][2] + s_red[0][3];
            const float e = s_red[1][0] + s_red[1][1] + s_red[1][2] + s_red[1][3];
            const float v = s_red[2][0] + s_red[2][1] + s_red[2][2] + s_red[2][3];
            const float p = __ldg(prev + c * G_ + ij);
            g_part[ij * C_ + c] = a + GAMMA_E * (p * e) - GAMMA_I * (p * v);
        }
        __syncthreads();   // s_red reuse safety across items
    }

    // Allow the dependent (finalize) grid to launch.
    asm volatile("griddepcontrol.launch_dependents;");
}

// One warp per ij: coalesced 64B load of the 16 partials, shuffle reduce,
// relu, broadcast-store to the 16 output channels (R6's proven finalize).
__global__ __launch_bounds__(256)
void cortex_finalize(float* __restrict__ out)
{
    const int gw   = (blockIdx.x * blockDim.x + threadIdx.x) >> 5;  // warp id
    const int lane = threadIdx.x & 31;

    // Wait until all memory from cortex_partial is visible.
    asm volatile("griddepcontrol.wait;" ::: "memory");

    if (gw >= G_) return;

    float v = (lane < C_) ? g_part[gw * C_ + lane] : 0.f;
    const unsigned FULL = 0xFFFFFFFFu;
    v += __shfl_down_sync(FULL, v, 8);
    v += __shfl_down_sync(FULL, v, 4);
    v += __shfl_down_sync(FULL, v, 2);
    v += __shfl_down_sync(FULL, v, 1);
    const float act = fmaxf(__shfl_sync(FULL, v, 0), 0.f);
    if (lane < C_)
        out[lane * G_ + gw] = act;
}

extern "C" void kernel_launch(void* const* d_in, const int* in_sizes, int n_in,
                              void* d_out, int out_size)
{
    const float* x    = (const float*)d_in[0];
    const float* prev = (const float*)d_in[1];
    const float* aw   = (const float*)d_in[2];
    const float* ew   = (const float*)d_in[3];
    const float* iw   = (const float*)d_in[4];
    const int*   rx   = (const int*)d_in[5];
    const int*   ry   = (const int*)d_in[6];
    float* out = (float*)d_out;

    cortex_partial<<<CTAS_, 128>>>(x, prev, aw, ew, iw, rx, ry);

    // Finalize with PDL (overlaps the partial's tail).
    const int warps_per_cta = 256 / 32;
    const int n_cta = (G_ + warps_per_cta - 1) / warps_per_cta;   // 162

    cudaLaunchConfig_t cfg = {};
    cfg.gridDim  = dim3(n_cta, 1, 1);
    cfg.blockDim = dim3(256, 1, 1);
    cfg.dynamicSmemBytes = 0;
    cudaLaunchAttribute attrs[1];
    attrs[0].id = cudaLaunchAttributeProgrammaticStreamSerialization;
    attrs[0].val.programmaticStreamSerializationAllowed = 1;
    cfg.attrs = attrs;
    cfg.numAttrs = 1;
    cudaLaunchKernelEx(&cfg, cortex_finalize, out);
}